// round 13
// baseline (speedup 1.0000x reference)
#include <cuda_runtime.h>
#include <math.h>
#include <stdint.h>

// ---------------- problem constants ----------------
#define NN   2207
#define EE   151215
#define BB   512
#define MID  8
#define G1   12
#define G2   4
#define KK   (G2*NN)      // 8828
#define F1   256
#define F2   64
#define EPSV 1e-5f
#define KSPLIT 8
#define KLEN 1104         // ceil(KK/KSPLIT)
#define CAP  192          // max in-degree capacity (Poisson(68.5): P(>192) ~ 0)

// ---------------- device scratch (no allocs allowed) ----------------
__device__ int   d_cnt[NN];
__device__ int2  d_bin[NN*CAP];           // {src, weight-bits}, row n at n*CAP
__device__ float d_a[NN*BB];              // agg/deg, [n][b]
__device__ float d_sums[BB], d_sumsq[BB];
__device__ float d_flat[KK*BB];           // [k][b], tf32-rounded values
__device__ float d_wt[KK*F1];             // fc1_w, tf32-rounded
__device__ float d_part[KSPLIT*BB*F1];    // split-K partials

__device__ __forceinline__ float bn_scale() { return 1.0f / sqrtf(1.0f + EPSV); }

__device__ __forceinline__ uint32_t f2tf32(float v) {
    uint32_t r;
    asm("cvt.rna.tf32.f32 %0, %1;" : "=r"(r) : "f"(v));
    return r;
}

// ---------------- K1: prep — zero counters + tf32-round fc1_w (grid 2207x1024 = 2259968) ----
__global__ void k_prep(const float* __restrict__ w) {
    int i = blockIdx.x * 1024 + threadIdx.x;
    d_wt[i] = __uint_as_float(f2tf32(w[i]));       // KK*F1 == 2207*1024 exactly
    if (i < NN) d_cnt[i] = 0;
    if (i < BB) { d_sums[i] = 0.f; d_sumsq[i] = 0.f; }
}

// ---------------- K2: self-counting scatter into padded bins, 4 edges/thread -----------------
__global__ void k_scatter(const int* __restrict__ ei, const float* __restrict__ ewp) {
    const int T = 148 * 256;
    int t0 = blockIdx.x * 256 + threadIdx.x;
    #pragma unroll 1
    for (int base = t0 * 4; base < EE; base += T * 4) {
        int src[4], dst[4];
        float w[4];
        int ne = min(4, EE - base);
        #pragma unroll
        for (int j = 0; j < 4; j++) {
            if (j < ne) {
                src[j] = ei[base + j];
                dst[j] = ei[EE + base + j];
                w[j]   = 1.0f / (1.0f + expf(-ewp[base + j]));
            }
        }
        int pos[4];
        #pragma unroll
        for (int j = 0; j < 4; j++)
            if (j < ne) pos[j] = atomicAdd(&d_cnt[dst[j]], 1);
        #pragma unroll
        for (int j = 0; j < 4; j++) {
            if (j < ne && pos[j] < CAP) {
                int2 p; p.x = src[j]; p.y = __float_as_int(w[j]);
                d_bin[dst[j] * CAP + pos[j]] = p;
            }
        }
    }
}

// ---------------- K3: SpMM (mean aggregation) + fused LN statistics --------------------------
// block = node, 128 threads, thread t owns batch lanes [4t, 4t+3]. After computing agg in
// registers, directly accumulates relu(a*w+b) sum/sumsq into d_sums/d_sumsq (saves a full
// 4.5MB re-read kernel).
__global__ void k_spmm(const float* __restrict__ x,
                       const float* __restrict__ sagew, const float* __restrict__ sageb) {
    int n = blockIdx.x;
    int t = threadIdx.x;
    __shared__ float s_w[MID], s_b[MID];
    if (t < MID) { s_w[t] = sagew[t]; s_b[t] = sageb[t]; }
    const float4* __restrict__ x4 = (const float4*)x;
    int cntraw = d_cnt[n];
    int cnt = min(cntraw, CAP);
    __shared__ int   ss[CAP];
    __shared__ float sw[CAP];
    for (int j = t; j < cnt; j += 128) {
        int2 p = d_bin[n * CAP + j];
        ss[j] = p.x;
        sw[j] = __int_as_float(p.y);
    }
    __syncthreads();
    float4 acc = make_float4(0.f, 0.f, 0.f, 0.f);
    int i = 0;
    for (; i + 4 <= cnt; i += 4) {
        float4 v0 = x4[ss[i + 0] * 128 + t];
        float4 v1 = x4[ss[i + 1] * 128 + t];
        float4 v2 = x4[ss[i + 2] * 128 + t];
        float4 v3 = x4[ss[i + 3] * 128 + t];
        float w0 = sw[i], w1 = sw[i + 1], w2 = sw[i + 2], w3 = sw[i + 3];
        acc.x += w0 * v0.x + w1 * v1.x + w2 * v2.x + w3 * v3.x;
        acc.y += w0 * v0.y + w1 * v1.y + w2 * v2.y + w3 * v3.y;
        acc.z += w0 * v0.z + w1 * v1.z + w2 * v2.z + w3 * v3.z;
        acc.w += w0 * v0.w + w1 * v1.w + w2 * v2.w + w3 * v3.w;
    }
    for (; i < cnt; i++) {
        float4 v = x4[ss[i] * 128 + t];
        float w = sw[i];
        acc.x += w * v.x; acc.y += w * v.y; acc.z += w * v.z; acc.w += w * v.w;
    }
    float dg = (float)cntraw;
    if (dg < 1.f) dg = 1.f;
    float inv = 1.f / dg;
    acc.x *= inv; acc.y *= inv; acc.z *= inv; acc.w *= inv;
    ((float4*)d_a)[n * 128 + t] = acc;

    // fused LN stats: per-lane sum/sumsq of relu(a*w_m + b_m) over m
    float4 sum = make_float4(0.f, 0.f, 0.f, 0.f);
    float4 ssq = make_float4(0.f, 0.f, 0.f, 0.f);
    #pragma unroll
    for (int m = 0; m < MID; m++) {
        float wm = s_w[m], bm = s_b[m];
        float hx = fmaxf(acc.x * wm + bm, 0.f);
        float hy = fmaxf(acc.y * wm + bm, 0.f);
        float hz = fmaxf(acc.z * wm + bm, 0.f);
        float hw = fmaxf(acc.w * wm + bm, 0.f);
        sum.x += hx; sum.y += hy; sum.z += hz; sum.w += hw;
        ssq.x += hx * hx; ssq.y += hy * hy; ssq.z += hz * hz; ssq.w += hw * hw;
    }
    int b0 = t * 4;
    atomicAdd(&d_sums[b0 + 0], sum.x);  atomicAdd(&d_sumsq[b0 + 0], ssq.x);
    atomicAdd(&d_sums[b0 + 1], sum.y);  atomicAdd(&d_sumsq[b0 + 1], ssq.y);
    atomicAdd(&d_sums[b0 + 2], sum.z);  atomicAdd(&d_sumsq[b0 + 2], ssq.z);
    atomicAdd(&d_sums[b0 + 3], sum.w);  atomicAdd(&d_sumsq[b0 + 3], ssq.w);
}

// ---------------- K4: fused finalize+SAGE+LN+gc1+bn1+gc2+bn2 -> flat[k][b] (tf32-rounded) ----
__global__ void k_flat(const float* __restrict__ sagew, const float* __restrict__ sageb,
                       const float* __restrict__ lng,  const float* __restrict__ lnb,
                       const float* __restrict__ g1w,  const float* __restrict__ g1b,
                       const float* __restrict__ bn1g, const float* __restrict__ bn1b,
                       const float* __restrict__ g2w,  const float* __restrict__ g2b,
                       const float* __restrict__ bn2g, const float* __restrict__ bn2b) {
    __shared__ float s_sw[MID], s_sb[MID], s_lg[MID], s_lb[MID];
    __shared__ float s_g1w[G1 * MID], s_g1b[G1], s_s1[G1], s_t1[G1];
    __shared__ float s_g2w[G2 * G1],  s_g2b[G2], s_s2[G2], s_t2[G2];
    int n = blockIdx.x;
    int t = threadIdx.x;
    float inv = bn_scale();
    if (t < MID) { s_sw[t] = sagew[t]; s_sb[t] = sageb[t]; s_lg[t] = lng[n * MID + t]; s_lb[t] = lnb[n * MID + t]; }
    if (t < G1 * MID) s_g1w[t] = g1w[t];
    if (t < G1) { s_g1b[t] = g1b[t]; s_s1[t] = bn1g[t] * inv; s_t1[t] = bn1b[t]; }
    if (t < G2 * G1) s_g2w[t] = g2w[t];
    if (t < G2) { s_g2b[t] = g2b[t]; s_s2[t] = bn2g[t] * inv; s_t2[t] = bn2b[t]; }
    __syncthreads();

    int b = t;
    const float cnt = (float)(NN * MID);
    float mu   = d_sums[b] / cnt;
    float var  = d_sumsq[b] / cnt - mu * mu;
    float rstd = rsqrtf(var + EPSV);
    float a = d_a[n * BB + b];
    float g[MID];
    #pragma unroll
    for (int m = 0; m < MID; m++) {
        float h = fmaxf(a * s_sw[m] + s_sb[m], 0.f);
        g[m] = (h - mu) * rstd * s_lg[m] + s_lb[m];
    }
    float y1[G1];
    #pragma unroll
    for (int o = 0; o < G1; o++) {
        float v = s_g1b[o];
        #pragma unroll
        for (int m = 0; m < MID; m++) v += s_g1w[o * MID + m] * g[m];
        v = fmaxf(v, 0.f);
        y1[o] = v * s_s1[o] + s_t1[o];
    }
    #pragma unroll
    for (int q = 0; q < G2; q++) {
        float v = s_g2b[q];
        #pragma unroll
        for (int o = 0; o < G1; o++) v += s_g2w[q * G1 + o] * y1[o];
        v = fmaxf(v, 0.f);
        v = v * s_s2[q] + s_t2[q];
        d_flat[(q * NN + n) * BB + b] = __uint_as_float(f2tf32(v));
    }
}

// ---------------- K5: fc1 GEMM, tf32 MMA, conflict-free smem (pitch 72), single buffer ------
__global__ void __launch_bounds__(128) k_gemm_tc() {
    __shared__ __align__(16) float As[32][72];   // 72%32==8 -> MMA bank = 8*tg+gq+c, distinct
    __shared__ __align__(16) float Bs[32][72];
    int tid  = threadIdx.x;
    int warp = tid >> 5, lane = tid & 31;
    int gq = lane >> 2, tg = lane & 3;
    int m0 = blockIdx.x * 64;
    int n0 = blockIdx.y * 64;
    int bz = blockIdx.z;
    int k0 = bz * KLEN;
    int k1 = min(k0 + KLEN, KK);
    int wm = warp * 16;
    int lr = tid >> 4;              // 0..7
    int lc = (tid & 15) << 2;       // 0,4,...,60
    float acc[8][4];
    #pragma unroll
    for (int i = 0; i < 8; i++)
        #pragma unroll
        for (int j = 0; j < 4; j++) acc[i][j] = 0.f;

    for (int kb = k0; kb < k1; kb += 32) {
        #pragma unroll
        for (int r = 0; r < 4; r++) {
            int kr = lr + r * 8;
            int kg = kb + kr;
            bool ok = (kg < k1);
            float4 va = ok ? *(const float4*)&d_flat[kg * BB + m0 + lc]
                           : make_float4(0.f, 0.f, 0.f, 0.f);
            float4 vb = ok ? *(const float4*)&d_wt[kg * F1 + n0 + lc]
                           : make_float4(0.f, 0.f, 0.f, 0.f);
            *(float4*)&As[kr][lc] = va;
            *(float4*)&Bs[kr][lc] = vb;
        }
        __syncthreads();
        #pragma unroll
        for (int ks = 0; ks < 32; ks += 8) {
            uint32_t a0 = __float_as_uint(As[ks + tg][wm + gq]);
            uint32_t a1 = __float_as_uint(As[ks + tg][wm + gq + 8]);
            uint32_t a2 = __float_as_uint(As[ks + tg + 4][wm + gq]);
            uint32_t a3 = __float_as_uint(As[ks + tg + 4][wm + gq + 8]);
            #pragma unroll
            for (int nf = 0; nf < 8; nf++) {
                uint32_t b0 = __float_as_uint(Bs[ks + tg][nf * 8 + gq]);
                uint32_t b1 = __float_as_uint(Bs[ks + tg + 4][nf * 8 + gq]);
                asm volatile(
                    "mma.sync.aligned.m16n8k8.row.col.f32.tf32.tf32.f32 "
                    "{%0,%1,%2,%3}, {%4,%5,%6,%7}, {%8,%9}, {%0,%1,%2,%3};\n"
                    : "+f"(acc[nf][0]), "+f"(acc[nf][1]), "+f"(acc[nf][2]), "+f"(acc[nf][3])
                    : "r"(a0), "r"(a1), "r"(a2), "r"(a3), "r"(b0), "r"(b1));
            }
        }
        __syncthreads();
    }
    float* out = d_part + bz * (BB * F1);
    int row0 = m0 + wm + gq;
    #pragma unroll
    for (int nf = 0; nf < 8; nf++) {
        int col = n0 + nf * 8 + 2 * tg;
        out[row0 * F1 + col]           = acc[nf][0];
        out[row0 * F1 + col + 1]       = acc[nf][1];
        out[(row0 + 8) * F1 + col]     = acc[nf][2];
        out[(row0 + 8) * F1 + col + 1] = acc[nf][3];
    }
}

// ---------------- K6: head ----------------
__global__ void k_head(const float* __restrict__ fc1b, const float* __restrict__ fbn1g,
                       const float* __restrict__ fbn1b, const float* __restrict__ fc2w,
                       const float* __restrict__ fc2b, const float* __restrict__ fbn2g,
                       const float* __restrict__ fbn2b, const float* __restrict__ outw,
                       const float* __restrict__ outb, float* __restrict__ out) {
    __shared__ float zs[F1];
    __shared__ float z2[F2];
    __shared__ float lg[2];
    int b = blockIdx.x, f = threadIdx.x;
    float inv = bn_scale();
    float v = 0.f;
    #pragma unroll
    for (int s = 0; s < KSPLIT; s++) v += d_part[s * (BB * F1) + b * F1 + f];
    v += fc1b[f];
    v = v * (fbn1g[f] * inv) + fbn1b[f];
    v = fmaxf(v, 0.f);
    zs[f] = v;
    __syncthreads();
    if (f < F2) {
        float w = 0.f;
        #pragma unroll 4
        for (int i = 0; i < F1; i++) w += zs[i] * fc2w[i * F2 + f];
        w += fc2b[f];
        w = w * (fbn2g[f] * inv) + fbn2b[f];
        w = fmaxf(w, 0.f);
        z2[f] = w;
    }
    __syncthreads();
    if (f < 2) {
        float l = 0.f;
        #pragma unroll
        for (int i = 0; i < F2; i++) l += z2[i] * outw[i * 2 + f];
        l += outb[f];
        lg[f] = l;
    }
    __syncthreads();
    if (f == 0) {
        float l0 = lg[0], l1 = lg[1];
        float m = fmaxf(l0, l1);
        float e0 = expf(l0 - m), e1 = expf(l1 - m);
        float s = 1.f / (e0 + e1);
        out[b * 2 + 0] = e0 * s;
        out[b * 2 + 1] = e1 * s;
    }
}

// ---------------- launch ----------------
extern "C" void kernel_launch(void* const* d_in, const int* in_sizes, int n_in,
                              void* d_out, int out_size) {
    const float* x     = (const float*)d_in[0];
    const int*   ei    = (const int*)d_in[1];     // int32 (JAX demotes int64)
    const float* ewp   = (const float*)d_in[2];
    const float* sagew = (const float*)d_in[3];
    const float* sageb = (const float*)d_in[5];
    const float* lng   = (const float*)d_in[6];
    const float* lnb   = (const float*)d_in[7];
    const float* g1w   = (const float*)d_in[8];
    const float* g1b   = (const float*)d_in[9];
    const float* bn1g  = (const float*)d_in[10];
    const float* bn1b  = (const float*)d_in[11];
    const float* g2w   = (const float*)d_in[12];
    const float* g2b   = (const float*)d_in[13];
    const float* bn2g  = (const float*)d_in[14];
    const float* bn2b  = (const float*)d_in[15];
    const float* fc1w  = (const float*)d_in[16];
    const float* fc1b  = (const float*)d_in[17];
    const float* fbn1g = (const float*)d_in[18];
    const float* fbn1b = (const float*)d_in[19];
    const float* fc2w  = (const float*)d_in[20];
    const float* fc2b  = (const float*)d_in[21];
    const float* fbn2g = (const float*)d_in[22];
    const float* fbn2b = (const float*)d_in[23];
    const float* outw  = (const float*)d_in[24];
    const float* outb  = (const float*)d_in[25];
    float* out = (float*)d_out;

    k_prep<<<2207, 1024>>>(fc1w);
    k_scatter<<<148, 256>>>(ei, ewp);
    k_spmm<<<NN, 128>>>(x, sagew, sageb);
    k_flat<<<NN, 512>>>(sagew, sageb, lng, lnb, g1w, g1b, bn1g, bn1b,
                        g2w, g2b, bn2g, bn2b);
    k_gemm_tc<<<dim3(BB / 64, F1 / 64, KSPLIT), 128>>>();
    k_head<<<BB, 256>>>(fc1b, fbn1g, fbn1b, fc2w, fc2b, fbn2g, fbn2b,
                        outw, outb, out);
}

// round 14
// speedup vs baseline: 1.5018x; 1.5018x over previous
#include <cuda_runtime.h>
#include <math.h>
#include <stdint.h>

// ---------------- problem constants ----------------
#define NN   2207
#define EE   151215
#define BB   512
#define MID  8
#define G1   12
#define G2   4
#define KK   (G2*NN)      // 8828
#define F1   256
#define F2   64
#define EPSV 1e-5f
#define KSPLIT 8
#define KLEN 1104         // ceil(KK/KSPLIT)
#define CAP  192          // max in-degree capacity (Poisson(68.5): P(>192) ~ 0)

// ---------------- device scratch (no allocs allowed) ----------------
__device__ int   d_cnt[NN];
__device__ int2  d_bin[NN*CAP];           // {src, weight-bits}, row n at n*CAP
__device__ float d_a[NN*BB];              // agg/deg, [n][b]
__device__ float d_sums[BB], d_sumsq[BB];
__device__ float d_flat[KK*BB];           // [k][b], tf32-rounded values
__device__ float d_wt[KK*F1];             // fc1_w, tf32-rounded
__device__ float d_part[KSPLIT*BB*F1];    // split-K partials

__device__ __forceinline__ float bn_scale() { return 1.0f / sqrtf(1.0f + EPSV); }

__device__ __forceinline__ uint32_t f2tf32(float v) {
    uint32_t r;
    asm("cvt.rna.tf32.f32 %0, %1;" : "=r"(r) : "f"(v));
    return r;
}

// ---------------- K1: prep — zero counters + tf32-round fc1_w (grid 2207x1024 = 2259968) ----
__global__ void k_prep(const float* __restrict__ w) {
    int i = blockIdx.x * 1024 + threadIdx.x;
    d_wt[i] = __uint_as_float(f2tf32(w[i]));       // KK*F1 == 2207*1024 exactly
    if (i < NN) d_cnt[i] = 0;
    if (i < BB) { d_sums[i] = 0.f; d_sumsq[i] = 0.f; }
}

// ---------------- K2: self-counting scatter into padded bins, 4 edges/thread -----------------
__global__ void k_scatter(const int* __restrict__ ei, const float* __restrict__ ewp) {
    const int T = 148 * 256;
    int t0 = blockIdx.x * 256 + threadIdx.x;
    #pragma unroll 1
    for (int base = t0 * 4; base < EE; base += T * 4) {
        int src[4], dst[4];
        float w[4];
        int ne = min(4, EE - base);
        #pragma unroll
        for (int j = 0; j < 4; j++) {
            if (j < ne) {
                src[j] = ei[base + j];
                dst[j] = ei[EE + base + j];
                w[j]   = 1.0f / (1.0f + expf(-ewp[base + j]));
            }
        }
        int pos[4];
        #pragma unroll
        for (int j = 0; j < 4; j++)
            if (j < ne) pos[j] = atomicAdd(&d_cnt[dst[j]], 1);
        #pragma unroll
        for (int j = 0; j < 4; j++) {
            if (j < ne && pos[j] < CAP) {
                int2 p; p.x = src[j]; p.y = __float_as_int(w[j]);
                d_bin[dst[j] * CAP + pos[j]] = p;
            }
        }
    }
}

// ---------------- K3: SpMM (mean aggregation), block = node, float4 lanes --------------------
__global__ void k_spmm(const float* __restrict__ x) {
    int n = blockIdx.x;
    int t = threadIdx.x;                 // 0..127, handles batch [4t, 4t+3]
    const float4* __restrict__ x4 = (const float4*)x;
    int cntraw = d_cnt[n];
    int cnt = min(cntraw, CAP);
    __shared__ int   ss[CAP];
    __shared__ float sw[CAP];
    for (int j = t; j < cnt; j += 128) {
        int2 p = d_bin[n * CAP + j];
        ss[j] = p.x;
        sw[j] = __int_as_float(p.y);
    }
    __syncthreads();
    float4 acc = make_float4(0.f, 0.f, 0.f, 0.f);
    int i = 0;
    for (; i + 4 <= cnt; i += 4) {
        float4 v0 = x4[ss[i + 0] * 128 + t];
        float4 v1 = x4[ss[i + 1] * 128 + t];
        float4 v2 = x4[ss[i + 2] * 128 + t];
        float4 v3 = x4[ss[i + 3] * 128 + t];
        float w0 = sw[i], w1 = sw[i + 1], w2 = sw[i + 2], w3 = sw[i + 3];
        acc.x += w0 * v0.x + w1 * v1.x + w2 * v2.x + w3 * v3.x;
        acc.y += w0 * v0.y + w1 * v1.y + w2 * v2.y + w3 * v3.y;
        acc.z += w0 * v0.z + w1 * v1.z + w2 * v2.z + w3 * v3.z;
        acc.w += w0 * v0.w + w1 * v1.w + w2 * v2.w + w3 * v3.w;
    }
    for (; i < cnt; i++) {
        float4 v = x4[ss[i] * 128 + t];
        float w = sw[i];
        acc.x += w * v.x; acc.y += w * v.y; acc.z += w * v.z; acc.w += w * v.w;
    }
    float dg = (float)cntraw;
    if (dg < 1.f) dg = 1.f;
    float inv = 1.f / dg;
    acc.x *= inv; acc.y *= inv; acc.z *= inv; acc.w *= inv;
    ((float4*)d_a)[n * 128 + t] = acc;
}

// ---------------- K4: LN statistics — 552 blocks x 512 thr, 4 nodes/thread -------------------
__global__ void k_stats(const float* __restrict__ sagew, const float* __restrict__ sageb) {
    __shared__ float s_w[MID], s_b[MID];
    int b = threadIdx.x;
    if (b < MID) { s_w[b] = sagew[b]; s_b[b] = sageb[b]; }
    __syncthreads();
    float sum = 0.f, ss = 0.f;
    int n0 = blockIdx.x * 4;
    #pragma unroll
    for (int r = 0; r < 4; r++) {
        int n = n0 + r;
        if (n >= NN) break;
        float a = d_a[n * BB + b];
        #pragma unroll
        for (int m = 0; m < MID; m++) {
            float h = fmaxf(a * s_w[m] + s_b[m], 0.f);
            sum += h;
            ss  += h * h;
        }
    }
    atomicAdd(&d_sums[b], sum);
    atomicAdd(&d_sumsq[b], ss);
}

// ---------------- K5: fused finalize+SAGE+LN+gc1+bn1+gc2+bn2 -> flat[k][b] (tf32-rounded) ----
__global__ void k_flat(const float* __restrict__ sagew, const float* __restrict__ sageb,
                       const float* __restrict__ lng,  const float* __restrict__ lnb,
                       const float* __restrict__ g1w,  const float* __restrict__ g1b,
                       const float* __restrict__ bn1g, const float* __restrict__ bn1b,
                       const float* __restrict__ g2w,  const float* __restrict__ g2b,
                       const float* __restrict__ bn2g, const float* __restrict__ bn2b) {
    __shared__ float s_sw[MID], s_sb[MID], s_lg[MID], s_lb[MID];
    __shared__ float s_g1w[G1 * MID], s_g1b[G1], s_s1[G1], s_t1[G1];
    __shared__ float s_g2w[G2 * G1],  s_g2b[G2], s_s2[G2], s_t2[G2];
    int n = blockIdx.x;
    int t = threadIdx.x;
    float inv = bn_scale();
    if (t < MID) { s_sw[t] = sagew[t]; s_sb[t] = sageb[t]; s_lg[t] = lng[n * MID + t]; s_lb[t] = lnb[n * MID + t]; }
    if (t < G1 * MID) s_g1w[t] = g1w[t];
    if (t < G1) { s_g1b[t] = g1b[t]; s_s1[t] = bn1g[t] * inv; s_t1[t] = bn1b[t]; }
    if (t < G2 * G1) s_g2w[t] = g2w[t];
    if (t < G2) { s_g2b[t] = g2b[t]; s_s2[t] = bn2g[t] * inv; s_t2[t] = bn2b[t]; }
    __syncthreads();

    int b = t;
    const float cnt = (float)(NN * MID);
    float mu   = d_sums[b] / cnt;
    float var  = d_sumsq[b] / cnt - mu * mu;
    float rstd = rsqrtf(var + EPSV);
    float a = d_a[n * BB + b];
    float g[MID];
    #pragma unroll
    for (int m = 0; m < MID; m++) {
        float h = fmaxf(a * s_sw[m] + s_sb[m], 0.f);
        g[m] = (h - mu) * rstd * s_lg[m] + s_lb[m];
    }
    float y1[G1];
    #pragma unroll
    for (int o = 0; o < G1; o++) {
        float v = s_g1b[o];
        #pragma unroll
        for (int m = 0; m < MID; m++) v += s_g1w[o * MID + m] * g[m];
        v = fmaxf(v, 0.f);
        y1[o] = v * s_s1[o] + s_t1[o];
    }
    #pragma unroll
    for (int q = 0; q < G2; q++) {
        float v = s_g2b[q];
        #pragma unroll
        for (int o = 0; o < G1; o++) v += s_g2w[q * G1 + o] * y1[o];
        v = fmaxf(v, 0.f);
        v = v * s_s2[q] + s_t2[q];
        d_flat[(q * NN + n) * BB + b] = __uint_as_float(f2tf32(v));
    }
}

// ---------------- K6: fc1 GEMM, tf32 MMA, conflict-free smem (pitch 72), single buffer ------
__global__ void __launch_bounds__(128) k_gemm_tc() {
    __shared__ __align__(16) float As[32][72];   // 72%32==8 -> MMA bank = 8*tg+gq+c, distinct
    __shared__ __align__(16) float Bs[32][72];
    int tid  = threadIdx.x;
    int warp = tid >> 5, lane = tid & 31;
    int gq = lane >> 2, tg = lane & 3;
    int m0 = blockIdx.x * 64;
    int n0 = blockIdx.y * 64;
    int bz = blockIdx.z;
    int k0 = bz * KLEN;
    int k1 = min(k0 + KLEN, KK);
    int wm = warp * 16;
    int lr = tid >> 4;              // 0..7
    int lc = (tid & 15) << 2;       // 0,4,...,60
    float acc[8][4];
    #pragma unroll
    for (int i = 0; i < 8; i++)
        #pragma unroll
        for (int j = 0; j < 4; j++) acc[i][j] = 0.f;

    for (int kb = k0; kb < k1; kb += 32) {
        #pragma unroll
        for (int r = 0; r < 4; r++) {
            int kr = lr + r * 8;
            int kg = kb + kr;
            bool ok = (kg < k1);
            float4 va = ok ? *(const float4*)&d_flat[kg * BB + m0 + lc]
                           : make_float4(0.f, 0.f, 0.f, 0.f);
            float4 vb = ok ? *(const float4*)&d_wt[kg * F1 + n0 + lc]
                           : make_float4(0.f, 0.f, 0.f, 0.f);
            *(float4*)&As[kr][lc] = va;
            *(float4*)&Bs[kr][lc] = vb;
        }
        __syncthreads();
        #pragma unroll
        for (int ks = 0; ks < 32; ks += 8) {
            uint32_t a0 = __float_as_uint(As[ks + tg][wm + gq]);
            uint32_t a1 = __float_as_uint(As[ks + tg][wm + gq + 8]);
            uint32_t a2 = __float_as_uint(As[ks + tg + 4][wm + gq]);
            uint32_t a3 = __float_as_uint(As[ks + tg + 4][wm + gq + 8]);
            #pragma unroll
            for (int nf = 0; nf < 8; nf++) {
                uint32_t b0 = __float_as_uint(Bs[ks + tg][nf * 8 + gq]);
                uint32_t b1 = __float_as_uint(Bs[ks + tg + 4][nf * 8 + gq]);
                asm volatile(
                    "mma.sync.aligned.m16n8k8.row.col.f32.tf32.tf32.f32 "
                    "{%0,%1,%2,%3}, {%4,%5,%6,%7}, {%8,%9}, {%0,%1,%2,%3};\n"
                    : "+f"(acc[nf][0]), "+f"(acc[nf][1]), "+f"(acc[nf][2]), "+f"(acc[nf][3])
                    : "r"(a0), "r"(a1), "r"(a2), "r"(a3), "r"(b0), "r"(b1));
            }
        }
        __syncthreads();
    }
    float* out = d_part + bz * (BB * F1);
    int row0 = m0 + wm + gq;
    #pragma unroll
    for (int nf = 0; nf < 8; nf++) {
        int col = n0 + nf * 8 + 2 * tg;
        out[row0 * F1 + col]           = acc[nf][0];
        out[row0 * F1 + col + 1]       = acc[nf][1];
        out[(row0 + 8) * F1 + col]     = acc[nf][2];
        out[(row0 + 8) * F1 + col + 1] = acc[nf][3];
    }
}

// ---------------- K7: head ----------------
__global__ void k_head(const float* __restrict__ fc1b, const float* __restrict__ fbn1g,
                       const float* __restrict__ fbn1b, const float* __restrict__ fc2w,
                       const float* __restrict__ fc2b, const float* __restrict__ fbn2g,
                       const float* __restrict__ fbn2b, const float* __restrict__ outw,
                       const float* __restrict__ outb, float* __restrict__ out) {
    __shared__ float zs[F1];
    __shared__ float z2[F2];
    __shared__ float lg[2];
    int b = blockIdx.x, f = threadIdx.x;
    float inv = bn_scale();
    float v = 0.f;
    #pragma unroll
    for (int s = 0; s < KSPLIT; s++) v += d_part[s * (BB * F1) + b * F1 + f];
    v += fc1b[f];
    v = v * (fbn1g[f] * inv) + fbn1b[f];
    v = fmaxf(v, 0.f);
    zs[f] = v;
    __syncthreads();
    if (f < F2) {
        float w = 0.f;
        #pragma unroll 4
        for (int i = 0; i < F1; i++) w += zs[i] * fc2w[i * F2 + f];
        w += fc2b[f];
        w = w * (fbn2g[f] * inv) + fbn2b[f];
        w = fmaxf(w, 0.f);
        z2[f] = w;
    }
    __syncthreads();
    if (f < 2) {
        float l = 0.f;
        #pragma unroll
        for (int i = 0; i < F2; i++) l += z2[i] * outw[i * 2 + f];
        l += outb[f];
        lg[f] = l;
    }
    __syncthreads();
    if (f == 0) {
        float l0 = lg[0], l1 = lg[1];
        float m = fmaxf(l0, l1);
        float e0 = expf(l0 - m), e1 = expf(l1 - m);
        float s = 1.f / (e0 + e1);
        out[b * 2 + 0] = e0 * s;
        out[b * 2 + 1] = e1 * s;
    }
}

// ---------------- launch ----------------
extern "C" void kernel_launch(void* const* d_in, const int* in_sizes, int n_in,
                              void* d_out, int out_size) {
    const float* x     = (const float*)d_in[0];
    const int*   ei    = (const int*)d_in[1];     // int32 (JAX demotes int64)
    const float* ewp   = (const float*)d_in[2];
    const float* sagew = (const float*)d_in[3];
    const float* sageb = (const float*)d_in[5];
    const float* lng   = (const float*)d_in[6];
    const float* lnb   = (const float*)d_in[7];
    const float* g1w   = (const float*)d_in[8];
    const float* g1b   = (const float*)d_in[9];
    const float* bn1g  = (const float*)d_in[10];
    const float* bn1b  = (const float*)d_in[11];
    const float* g2w   = (const float*)d_in[12];
    const float* g2b   = (const float*)d_in[13];
    const float* bn2g  = (const float*)d_in[14];
    const float* bn2b  = (const float*)d_in[15];
    const float* fc1w  = (const float*)d_in[16];
    const float* fc1b  = (const float*)d_in[17];
    const float* fbn1g = (const float*)d_in[18];
    const float* fbn1b = (const float*)d_in[19];
    const float* fc2w  = (const float*)d_in[20];
    const float* fc2b  = (const float*)d_in[21];
    const float* fbn2g = (const float*)d_in[22];
    const float* fbn2b = (const float*)d_in[23];
    const float* outw  = (const float*)d_in[24];
    const float* outb  = (const float*)d_in[25];
    float* out = (float*)d_out;

    k_prep<<<2207, 1024>>>(fc1w);
    k_scatter<<<148, 256>>>(ei, ewp);
    k_spmm<<<NN, 128>>>(x);
    k_stats<<<(NN + 3) / 4, 512>>>(sagew, sageb);
    k_flat<<<NN, 512>>>(sagew, sageb, lng, lnb, g1w, g1b, bn1g, bn1b,
                        g2w, g2b, bn2g, bn2b);
    k_gemm_tc<<<dim3(BB / 64, F1 / 64, KSPLIT), 128>>>();
    k_head<<<BB, 256>>>(fc1b, fbn1g, fbn1b, fc2w, fc2b, fbn2g, fbn2b,
                        outw, outb, out);
}

// round 17
// speedup vs baseline: 1.5561x; 1.0362x over previous
#include <cuda_runtime.h>
#include <math.h>
#include <stdint.h>

// ---------------- problem constants ----------------
#define NN   2207
#define EE   151215
#define BB   512
#define MID  8
#define G1   12
#define G2   4
#define KK   (G2*NN)      // 8828
#define F1   256
#define F2   64
#define EPSV 1e-5f
#define KSPLIT 8
#define KLEN 1104         // ceil(KK/KSPLIT)
#define CAP  192          // max in-degree capacity (Poisson(68.5): P(>192) ~ 0)

// ---------------- device scratch (no allocs allowed) ----------------
__device__ int   d_cnt[NN];
__device__ int2  d_bin[NN*CAP];           // {src, weight-bits}, row n at n*CAP
__device__ float d_a[NN*BB];              // agg/deg, [n][b]
__device__ float d_sums[BB], d_sumsq[BB];
__device__ float d_flat[KK*BB];           // [k][b], tf32-rounded values
__device__ float d_wt[KK*F1];             // fc1_w, tf32-rounded
__device__ float d_part[KSPLIT*BB*F1];    // split-K partials

__device__ __forceinline__ float bn_scale() { return 1.0f / sqrtf(1.0f + EPSV); }

__device__ __forceinline__ uint32_t f2tf32(float v) {
    uint32_t r;
    asm("cvt.rna.tf32.f32 %0, %1;" : "=r"(r) : "f"(v));
    return r;
}

// ---------------- K1: prep — zero counters + tf32-round fc1_w (grid 2207x1024 = 2259968) ----
__global__ void k_prep(const float* __restrict__ w) {
    int i = blockIdx.x * 1024 + threadIdx.x;
    d_wt[i] = __uint_as_float(f2tf32(w[i]));       // KK*F1 == 2207*1024 exactly
    if (i < NN) d_cnt[i] = 0;
    if (i < BB) { d_sums[i] = 0.f; d_sumsq[i] = 0.f; }
}

// ---------------- K2: self-counting scatter into padded bins, 4 edges/thread -----------------
__global__ void k_scatter(const int* __restrict__ ei, const float* __restrict__ ewp) {
    const int T = 148 * 256;
    int t0 = blockIdx.x * 256 + threadIdx.x;
    #pragma unroll 1
    for (int base = t0 * 4; base < EE; base += T * 4) {
        int src[4], dst[4];
        float w[4];
        int ne = min(4, EE - base);
        #pragma unroll
        for (int j = 0; j < 4; j++) {
            if (j < ne) {
                src[j] = ei[base + j];
                dst[j] = ei[EE + base + j];
                w[j]   = 1.0f / (1.0f + expf(-ewp[base + j]));
            }
        }
        int pos[4];
        #pragma unroll
        for (int j = 0; j < 4; j++)
            if (j < ne) pos[j] = atomicAdd(&d_cnt[dst[j]], 1);
        #pragma unroll
        for (int j = 0; j < 4; j++) {
            if (j < ne && pos[j] < CAP) {
                int2 p; p.x = src[j]; p.y = __float_as_int(w[j]);
                d_bin[dst[j] * CAP + pos[j]] = p;
            }
        }
    }
}

// ---------------- K3: SpMM (mean aggregation), block = node, float4 lanes --------------------
__global__ void k_spmm(const float* __restrict__ x) {
    int n = blockIdx.x;
    int t = threadIdx.x;                 // 0..127, handles batch [4t, 4t+3]
    const float4* __restrict__ x4 = (const float4*)x;
    int cntraw = d_cnt[n];
    int cnt = min(cntraw, CAP);
    __shared__ int   ss[CAP];
    __shared__ float sw[CAP];
    for (int j = t; j < cnt; j += 128) {
        int2 p = d_bin[n * CAP + j];
        ss[j] = p.x;
        sw[j] = __int_as_float(p.y);
    }
    __syncthreads();
    float4 acc = make_float4(0.f, 0.f, 0.f, 0.f);
    int i = 0;
    for (; i + 4 <= cnt; i += 4) {
        float4 v0 = x4[ss[i + 0] * 128 + t];
        float4 v1 = x4[ss[i + 1] * 128 + t];
        float4 v2 = x4[ss[i + 2] * 128 + t];
        float4 v3 = x4[ss[i + 3] * 128 + t];
        float w0 = sw[i], w1 = sw[i + 1], w2 = sw[i + 2], w3 = sw[i + 3];
        acc.x += w0 * v0.x + w1 * v1.x + w2 * v2.x + w3 * v3.x;
        acc.y += w0 * v0.y + w1 * v1.y + w2 * v2.y + w3 * v3.y;
        acc.z += w0 * v0.z + w1 * v1.z + w2 * v2.z + w3 * v3.z;
        acc.w += w0 * v0.w + w1 * v1.w + w2 * v2.w + w3 * v3.w;
    }
    for (; i < cnt; i++) {
        float4 v = x4[ss[i] * 128 + t];
        float w = sw[i];
        acc.x += w * v.x; acc.y += w * v.y; acc.z += w * v.z; acc.w += w * v.w;
    }
    float dg = (float)cntraw;
    if (dg < 1.f) dg = 1.f;
    float inv = 1.f / dg;
    acc.x *= inv; acc.y *= inv; acc.z *= inv; acc.w *= inv;
    ((float4*)d_a)[n * 128 + t] = acc;
}

// ---------------- K4: LN statistics — 552 blocks x 512 thr, 4 nodes/thread -------------------
__global__ void k_stats(const float* __restrict__ sagew, const float* __restrict__ sageb) {
    __shared__ float s_w[MID], s_b[MID];
    int b = threadIdx.x;
    if (b < MID) { s_w[b] = sagew[b]; s_b[b] = sageb[b]; }
    __syncthreads();
    float sum = 0.f, ss = 0.f;
    int n0 = blockIdx.x * 4;
    #pragma unroll
    for (int r = 0; r < 4; r++) {
        int n = n0 + r;
        if (n >= NN) break;
        float a = d_a[n * BB + b];
        #pragma unroll
        for (int m = 0; m < MID; m++) {
            float h = fmaxf(a * s_w[m] + s_b[m], 0.f);
            sum += h;
            ss  += h * h;
        }
    }
    atomicAdd(&d_sums[b], sum);
    atomicAdd(&d_sumsq[b], ss);
}

// ---------------- K5: fused finalize+SAGE+LN+gc1+bn1+gc2+bn2 -> flat[k][b] (tf32-rounded) ----
// 256 threads, thread t owns batch lanes {2t, 2t+1} (float2). Halves L1 wavefront count vs
// the 512-thread scalar version (weight LDS amortized over 2 lanes, LDG/STG are 64-bit).
__global__ void k_flat(const float* __restrict__ sagew, const float* __restrict__ sageb,
                       const float* __restrict__ lng,  const float* __restrict__ lnb,
                       const float* __restrict__ g1w,  const float* __restrict__ g1b,
                       const float* __restrict__ bn1g, const float* __restrict__ bn1b,
                       const float* __restrict__ g2w,  const float* __restrict__ g2b,
                       const float* __restrict__ bn2g, const float* __restrict__ bn2b) {
    __shared__ float s_sw[MID], s_sb[MID], s_lg[MID], s_lb[MID];
    __shared__ float s_g1w[G1 * MID], s_g1b[G1], s_s1[G1], s_t1[G1];
    __shared__ float s_g2w[G2 * G1],  s_g2b[G2], s_s2[G2], s_t2[G2];
    int n = blockIdx.x;
    int t = threadIdx.x;                 // 0..255
    float inv = bn_scale();
    if (t < MID) { s_sw[t] = sagew[t]; s_sb[t] = sageb[t]; s_lg[t] = lng[n * MID + t]; s_lb[t] = lnb[n * MID + t]; }
    if (t < G1 * MID) s_g1w[t] = g1w[t];
    if (t < G1) { s_g1b[t] = g1b[t]; s_s1[t] = bn1g[t] * inv; s_t1[t] = bn1b[t]; }
    if (t < G2 * G1) s_g2w[t] = g2w[t];
    if (t < G2) { s_g2b[t] = g2b[t]; s_s2[t] = bn2g[t] * inv; s_t2[t] = bn2b[t]; }
    __syncthreads();

    const float cnt = (float)(NN * MID);
    const float2* __restrict__ sums2  = (const float2*)d_sums;
    const float2* __restrict__ sumsq2 = (const float2*)d_sumsq;
    float2 s  = sums2[t];
    float2 sq = sumsq2[t];
    float mux = s.x / cnt, muy = s.y / cnt;
    float rsx = rsqrtf(sq.x / cnt - mux * mux + EPSV);
    float rsy = rsqrtf(sq.y / cnt - muy * muy + EPSV);
    float2 a = ((const float2*)d_a)[n * 256 + t];

    float gx[MID], gy[MID];
    #pragma unroll
    for (int m = 0; m < MID; m++) {
        float wm = s_sw[m], bm = s_sb[m];
        float lg = s_lg[m], lb = s_lb[m];
        float hx = fmaxf(a.x * wm + bm, 0.f);
        float hy = fmaxf(a.y * wm + bm, 0.f);
        gx[m] = (hx - mux) * rsx * lg + lb;
        gy[m] = (hy - muy) * rsy * lg + lb;
    }
    float y1x[G1], y1y[G1];
    #pragma unroll
    for (int o = 0; o < G1; o++) {
        float vx = s_g1b[o], vy = vx;
        #pragma unroll
        for (int m = 0; m < MID; m++) {
            float w = s_g1w[o * MID + m];
            vx += w * gx[m];
            vy += w * gy[m];
        }
        vx = fmaxf(vx, 0.f); vy = fmaxf(vy, 0.f);
        float sc = s_s1[o], tb = s_t1[o];
        y1x[o] = vx * sc + tb;
        y1y[o] = vy * sc + tb;
    }
    float2* __restrict__ flat2 = (float2*)d_flat;
    #pragma unroll
    for (int q = 0; q < G2; q++) {
        float vx = s_g2b[q], vy = vx;
        #pragma unroll
        for (int o = 0; o < G1; o++) {
            float w = s_g2w[q * G1 + o];
            vx += w * y1x[o];
            vy += w * y1y[o];
        }
        vx = fmaxf(vx, 0.f); vy = fmaxf(vy, 0.f);
        float sc = s_s2[q], tb = s_t2[q];
        vx = vx * sc + tb;
        vy = vy * sc + tb;
        float2 outv;
        outv.x = __uint_as_float(f2tf32(vx));
        outv.y = __uint_as_float(f2tf32(vy));
        flat2[(q * NN + n) * 256 + t] = outv;
    }
}

// ---------------- K6: fc1 GEMM, tf32 MMA, conflict-free smem (pitch 72), single buffer ------
__global__ void __launch_bounds__(128) k_gemm_tc() {
    __shared__ __align__(16) float As[32][72];   // 72%32==8 -> MMA bank = 8*tg+gq+c, distinct
    __shared__ __align__(16) float Bs[32][72];
    int tid  = threadIdx.x;
    int warp = tid >> 5, lane = tid & 31;
    int gq = lane >> 2, tg = lane & 3;
    int m0 = blockIdx.x * 64;
    int n0 = blockIdx.y * 64;
    int bz = blockIdx.z;
    int k0 = bz * KLEN;
    int k1 = min(k0 + KLEN, KK);
    int wm = warp * 16;
    int lr = tid >> 4;              // 0..7
    int lc = (tid & 15) << 2;       // 0,4,...,60
    float acc[8][4];
    #pragma unroll
    for (int i = 0; i < 8; i++)
        #pragma unroll
        for (int j = 0; j < 4; j++) acc[i][j] = 0.f;

    for (int kb = k0; kb < k1; kb += 32) {
        #pragma unroll
        for (int r = 0; r < 4; r++) {
            int kr = lr + r * 8;
            int kg = kb + kr;
            bool ok = (kg < k1);
            float4 va = ok ? *(const float4*)&d_flat[kg * BB + m0 + lc]
                           : make_float4(0.f, 0.f, 0.f, 0.f);
            float4 vb = ok ? *(const float4*)&d_wt[kg * F1 + n0 + lc]
                           : make_float4(0.f, 0.f, 0.f, 0.f);
            *(float4*)&As[kr][lc] = va;
            *(float4*)&Bs[kr][lc] = vb;
        }
        __syncthreads();
        #pragma unroll
        for (int ks = 0; ks < 32; ks += 8) {
            uint32_t a0 = __float_as_uint(As[ks + tg][wm + gq]);
            uint32_t a1 = __float_as_uint(As[ks + tg][wm + gq + 8]);
            uint32_t a2 = __float_as_uint(As[ks + tg + 4][wm + gq]);
            uint32_t a3 = __float_as_uint(As[ks + tg + 4][wm + gq + 8]);
            #pragma unroll
            for (int nf = 0; nf < 8; nf++) {
                uint32_t b0 = __float_as_uint(Bs[ks + tg][nf * 8 + gq]);
                uint32_t b1 = __float_as_uint(Bs[ks + tg + 4][nf * 8 + gq]);
                asm volatile(
                    "mma.sync.aligned.m16n8k8.row.col.f32.tf32.tf32.f32 "
                    "{%0,%1,%2,%3}, {%4,%5,%6,%7}, {%8,%9}, {%0,%1,%2,%3};\n"
                    : "+f"(acc[nf][0]), "+f"(acc[nf][1]), "+f"(acc[nf][2]), "+f"(acc[nf][3])
                    : "r"(a0), "r"(a1), "r"(a2), "r"(a3), "r"(b0), "r"(b1));
            }
        }
        __syncthreads();
    }
    float* out = d_part + bz * (BB * F1);
    int row0 = m0 + wm + gq;
    #pragma unroll
    for (int nf = 0; nf < 8; nf++) {
        int col = n0 + nf * 8 + 2 * tg;
        out[row0 * F1 + col]           = acc[nf][0];
        out[row0 * F1 + col + 1]       = acc[nf][1];
        out[(row0 + 8) * F1 + col]     = acc[nf][2];
        out[(row0 + 8) * F1 + col + 1] = acc[nf][3];
    }
}

// ---------------- K7: head ----------------
__global__ void k_head(const float* __restrict__ fc1b, const float* __restrict__ fbn1g,
                       const float* __restrict__ fbn1b, const float* __restrict__ fc2w,
                       const float* __restrict__ fc2b, const float* __restrict__ fbn2g,
                       const float* __restrict__ fbn2b, const float* __restrict__ outw,
                       const float* __restrict__ outb, float* __restrict__ out) {
    __shared__ float zs[F1];
    __shared__ float z2[F2];
    __shared__ float lg[2];
    int b = blockIdx.x, f = threadIdx.x;
    float inv = bn_scale();
    float v = 0.f;
    #pragma unroll
    for (int s = 0; s < KSPLIT; s++) v += d_part[s * (BB * F1) + b * F1 + f];
    v += fc1b[f];
    v = v * (fbn1g[f] * inv) + fbn1b[f];
    v = fmaxf(v, 0.f);
    zs[f] = v;
    __syncthreads();
    if (f < F2) {
        float w = 0.f;
        #pragma unroll 4
        for (int i = 0; i < F1; i++) w += zs[i] * fc2w[i * F2 + f];
        w += fc2b[f];
        w = w * (fbn2g[f] * inv) + fbn2b[f];
        w = fmaxf(w, 0.f);
        z2[f] = w;
    }
    __syncthreads();
    if (f < 2) {
        float l = 0.f;
        #pragma unroll
        for (int i = 0; i < F2; i++) l += z2[i] * outw[i * 2 + f];
        l += outb[f];
        lg[f] = l;
    }
    __syncthreads();
    if (f == 0) {
        float l0 = lg[0], l1 = lg[1];
        float m = fmaxf(l0, l1);
        float e0 = expf(l0 - m), e1 = expf(l1 - m);
        float s = 1.f / (e0 + e1);
        out[b * 2 + 0] = e0 * s;
        out[b * 2 + 1] = e1 * s;
    }
}

// ---------------- launch ----------------
extern "C" void kernel_launch(void* const* d_in, const int* in_sizes, int n_in,
                              void* d_out, int out_size) {
    const float* x     = (const float*)d_in[0];
    const int*   ei    = (const int*)d_in[1];     // int32 (JAX demotes int64)
    const float* ewp   = (const float*)d_in[2];
    const float* sagew = (const float*)d_in[3];
    const float* sageb = (const float*)d_in[5];
    const float* lng   = (const float*)d_in[6];
    const float* lnb   = (const float*)d_in[7];
    const float* g1w   = (const float*)d_in[8];
    const float* g1b   = (const float*)d_in[9];
    const float* bn1g  = (const float*)d_in[10];
    const float* bn1b  = (const float*)d_in[11];
    const float* g2w   = (const float*)d_in[12];
    const float* g2b   = (const float*)d_in[13];
    const float* bn2g  = (const float*)d_in[14];
    const float* bn2b  = (const float*)d_in[15];
    const float* fc1w  = (const float*)d_in[16];
    const float* fc1b  = (const float*)d_in[17];
    const float* fbn1g = (const float*)d_in[18];
    const float* fbn1b = (const float*)d_in[19];
    const float* fc2w  = (const float*)d_in[20];
    const float* fc2b  = (const float*)d_in[21];
    const float* fbn2g = (const float*)d_in[22];
    const float* fbn2b = (const float*)d_in[23];
    const float* outw  = (const float*)d_in[24];
    const float* outb  = (const float*)d_in[25];
    float* out = (float*)d_out;

    k_prep<<<2207, 1024>>>(fc1w);
    k_scatter<<<148, 256>>>(ei, ewp);
    k_spmm<<<NN, 128>>>(x);
    k_stats<<<(NN + 3) / 4, 512>>>(sagew, sageb);
    k_flat<<<NN, 256>>>(sagew, sageb, lng, lnb, g1w, g1b, bn1g, bn1b,
                        g2w, g2b, bn2g, bn2b);
    k_gemm_tc<<<dim3(BB / 64, F1 / 64, KSPLIT), 128>>>();
    k_head<<<BB, 256>>>(fc1b, fbn1g, fbn1b, fc2w, fc2b, fbn2g, fbn2b,
                        outw, outb, out);
}